// round 3
// baseline (speedup 1.0000x reference)
#include <cuda_runtime.h>

#define N_NODES 100000
#define IN_DIM  1024
#define OUT_DIM 256
#define NNZ_X   3200000
#define NNZ_ADJ 3200000

#define SCAN_B    1024
#define N_SCANBLK ((N_NODES + SCAN_B - 1) / SCAN_B)   // 98

#define CHUNK1       32                                // W columns cached in smem
#define NCHUNK1      (OUT_DIM / CHUNK1)                // 8
#define SMEM1_BYTES  (IN_DIM * CHUNK1 * 4)             // 128 KB
#define ROWS1        ((N_NODES + 147) / 148)           // rows per spmm1 block

// ---------------- scratch (__device__ globals; no allocs allowed) ----------
__device__ float g_xw[(size_t)N_NODES * OUT_DIM];      // 102.4 MB

__device__ int   g_counts_x[N_NODES];
__device__ int   g_counts_a[N_NODES];
__device__ int   g_offs_x[N_NODES + 1];
__device__ int   g_offs_a[N_NODES + 1];
__device__ int   g_bsums_x[N_SCANBLK];
__device__ int   g_bsums_a[N_SCANBLK];
__device__ int2  g_cx[NNZ_X];                          // (col, val-bits)
__device__ int2  g_ca[NNZ_ADJ];

// ---------------- zero both counter arrays ---------------------------------
__global__ void zero2_kernel(int* __restrict__ a, int* __restrict__ b) {
    int i = blockIdx.x * blockDim.x + threadIdx.x;
    int stride = gridDim.x * blockDim.x;
    for (int j = i; j < N_NODES; j += stride) { a[j] = 0; b[j] = 0; }
}

// ---------------- fused histogram of both row arrays ------------------------
__global__ void hist_both_kernel(const int* __restrict__ xr, const int* __restrict__ ar,
                                 int* __restrict__ cx, int* __restrict__ ca) {
    int i = blockIdx.x * blockDim.x + threadIdx.x;
    if (i < NNZ_X)   atomicAdd(&cx[xr[i]], 1);
    if (i < NNZ_ADJ) atomicAdd(&ca[ar[i]], 1);
}

// ---------------- scan A: per-block exclusive scan (both arrays, grid.y) ----
__global__ void scanA_kernel(const int* __restrict__ cx, const int* __restrict__ ca,
                             int* __restrict__ ox, int* __restrict__ oa,
                             int* __restrict__ bx, int* __restrict__ ba) {
    const int* counts = blockIdx.y ? ca : cx;
    int* offs  = blockIdx.y ? oa : ox;
    int* bsums = blockIdx.y ? ba : bx;
    __shared__ int sm[SCAN_B];
    int t = threadIdx.x;
    int i = blockIdx.x * SCAN_B + t;
    int v = (i < N_NODES) ? counts[i] : 0;
    sm[t] = v;
    __syncthreads();
    for (int d = 1; d < SCAN_B; d <<= 1) {
        int add = (t >= d) ? sm[t - d] : 0;
        __syncthreads();
        sm[t] += add;
        __syncthreads();
    }
    int incl = sm[t];
    if (i < N_NODES) offs[i] = incl - v;
    if (t == SCAN_B - 1) bsums[blockIdx.x] = incl;
}

// ---------------- scan B: parallel exclusive scan of 98 block sums ----------
__global__ void scanB_kernel(int* __restrict__ bx, int* __restrict__ ba) {
    int* bsums = blockIdx.x ? ba : bx;
    __shared__ int sm[128];
    int t = threadIdx.x;
    int v = (t < N_SCANBLK) ? bsums[t] : 0;
    sm[t] = v;
    __syncthreads();
    for (int d = 1; d < 128; d <<= 1) {
        int add = (t >= d) ? sm[t - d] : 0;
        __syncthreads();
        sm[t] += add;
        __syncthreads();
    }
    if (t < N_SCANBLK) bsums[t] = sm[t] - v;   // exclusive
}

// ---------------- scan C: add block offsets ---------------------------------
__global__ void scanC_kernel(int* __restrict__ ox, int* __restrict__ oa,
                             const int* __restrict__ bx, const int* __restrict__ ba) {
    int* offs = blockIdx.y ? oa : ox;
    const int* bsums = blockIdx.y ? ba : bx;
    int i = blockIdx.x * SCAN_B + threadIdx.x;
    if (i < N_NODES) offs[i] += bsums[blockIdx.x];
    if (i == 0) offs[N_NODES] = blockIdx.y ? NNZ_ADJ : NNZ_X;
}

// ---------------- fused scatter COO -> CSR (int2 payload) -------------------
// counts[] still holds the histogram; atomicSub turns it into a fill cursor
// (ends at 0). Within-row order is reversed -> math identical.
__global__ void scatter_both_kernel(
        const int* __restrict__ xr, const int* __restrict__ xc, const float* __restrict__ xv,
        const int* __restrict__ ar, const int* __restrict__ ac, const float* __restrict__ av,
        const int* __restrict__ ox, const int* __restrict__ oa,
        int* __restrict__ cntx, int* __restrict__ cnta,
        int2* __restrict__ cx, int2* __restrict__ ca) {
    int i = blockIdx.x * blockDim.x + threadIdx.x;
    if (i < NNZ_X) {
        int r = xr[i];
        int p = ox[r] + atomicSub(&cntx[r], 1) - 1;
        cx[p] = make_int2(xc[i], __float_as_int(xv[i]));
    }
    if (i < NNZ_ADJ) {
        int r = ar[i];
        int p = oa[r] + atomicSub(&cnta[r], 1) - 1;
        ca[p] = make_int2(ac[i], __float_as_int(av[i]));
    }
}

// ---------------- SpMM1: smem-cached W chunk, warp per row ------------------
// grid = (148, 8). Each block caches W[:, chunk*32 .. +32) (128 KB) in smem,
// then sweeps its row range. Lane j handles output column chunk*32 + j.
__global__ void __launch_bounds__(512, 1)
spmm1_kernel(const int* __restrict__ offs, const int2* __restrict__ cdata,
             const float* __restrict__ W, float* __restrict__ xw) {
    extern __shared__ float smW[];                 // IN_DIM x CHUNK1
    __shared__ int2 stage[16][32];
    int wid  = threadIdx.x >> 5;
    int lane = threadIdx.x & 31;
    int c0   = blockIdx.y * CHUNK1;

    // fill W chunk: warp per row group, coalesced 128B loads
    for (int r = wid; r < IN_DIM; r += 16)
        smW[r * CHUNK1 + lane] = W[r * OUT_DIM + c0 + lane];
    __syncthreads();

    int row0 = blockIdx.x * ROWS1;
    int row1 = min(row0 + ROWS1, N_NODES);
    for (int row = row0 + wid; row < row1; row += 16) {
        int beg = offs[row];
        int end = offs[row + 1];
        float acc = 0.f;
        for (int base = beg; base < end; base += 32) {
            int k = base + lane;
            stage[wid][lane] = (k < end) ? cdata[k] : make_int2(0, 0);
            __syncwarp();
            int m = min(32, end - base);
            if (m == 32) {
#pragma unroll
                for (int t = 0; t < 32; t++) {
                    int2 cv = stage[wid][t];
                    acc = fmaf(__int_as_float(cv.y), smW[cv.x * CHUNK1 + lane], acc);
                }
            } else {
                for (int t = 0; t < m; t++) {
                    int2 cv = stage[wid][t];
                    acc = fmaf(__int_as_float(cv.y), smW[cv.x * CHUNK1 + lane], acc);
                }
            }
            __syncwarp();
        }
        xw[(size_t)row * OUT_DIM + c0 + lane] = acc;
    }
}

// ---------------- SpMM2 + ReLU: warp per row, half the columns per launch ---
// Launched twice (half = 0, 1); each pass's xw footprint is 51 MB -> L2-resident.
__global__ void __launch_bounds__(256, 8)
spmm2_kernel(const int* __restrict__ offs, const int2* __restrict__ cdata,
             const float* __restrict__ xw, float* __restrict__ out, int half) {
    __shared__ int2 stage[8][32];
    int wid  = threadIdx.x >> 5;
    int lane = threadIdx.x & 31;
    int row  = blockIdx.x * 8 + wid;
    if (row >= N_NODES) return;

    int beg = offs[row];
    int end = offs[row + 1];
    int coff = half * 128 + lane;

    float a0 = 0.f, a1 = 0.f, a2 = 0.f, a3 = 0.f;
    for (int base = beg; base < end; base += 32) {
        int k = base + lane;
        stage[wid][lane] = (k < end) ? cdata[k] : make_int2(0, 0);
        __syncwarp();
        int m = min(32, end - base);
        for (int t = 0; t < m; t++) {
            int2 cv = stage[wid][t];
            float vv = __int_as_float(cv.y);
            const float* s = xw + (size_t)cv.x * OUT_DIM + coff;
            a0 = fmaf(vv, __ldg(s),      a0);
            a1 = fmaf(vv, __ldg(s + 32), a1);
            a2 = fmaf(vv, __ldg(s + 64), a2);
            a3 = fmaf(vv, __ldg(s + 96), a3);
        }
        __syncwarp();
    }

    float* d = out + (size_t)row * OUT_DIM + coff;
    d[0]  = fmaxf(a0, 0.f);
    d[32] = fmaxf(a1, 0.f);
    d[64] = fmaxf(a2, 0.f);
    d[96] = fmaxf(a3, 0.f);
}

// ---------------------------------------------------------------------------
extern "C" void kernel_launch(void* const* d_in, const int* in_sizes, int n_in,
                              void* d_out, int out_size) {
    const int*   x_rows   = (const int*)  d_in[0];
    const int*   x_cols   = (const int*)  d_in[1];
    const float* x_vals   = (const float*)d_in[2];
    const int*   adj_rows = (const int*)  d_in[3];
    const int*   adj_cols = (const int*)  d_in[4];
    const float* adj_vals = (const float*)d_in[5];
    const float* W        = (const float*)d_in[6];
    float*       out      = (float*)d_out;

    float *xw; int *cntx, *cnta, *ox, *oa, *bx, *ba; int2 *cx, *ca;
    cudaGetSymbolAddress((void**)&xw,   g_xw);
    cudaGetSymbolAddress((void**)&cntx, g_counts_x);
    cudaGetSymbolAddress((void**)&cnta, g_counts_a);
    cudaGetSymbolAddress((void**)&ox,   g_offs_x);
    cudaGetSymbolAddress((void**)&oa,   g_offs_a);
    cudaGetSymbolAddress((void**)&bx,   g_bsums_x);
    cudaGetSymbolAddress((void**)&ba,   g_bsums_a);
    cudaGetSymbolAddress((void**)&cx,   g_cx);
    cudaGetSymbolAddress((void**)&ca,   g_ca);

    const int nnz_blocks = (NNZ_X + 255) / 256;

    // build phase
    zero2_kernel<<<196, 512>>>(cntx, cnta);
    hist_both_kernel<<<nnz_blocks, 256>>>(x_rows, adj_rows, cntx, cnta);
    scanA_kernel<<<dim3(N_SCANBLK, 2), SCAN_B>>>(cntx, cnta, ox, oa, bx, ba);
    scanB_kernel<<<2, 128>>>(bx, ba);
    scanC_kernel<<<dim3(N_SCANBLK, 2), SCAN_B>>>(ox, oa, bx, ba);
    scatter_both_kernel<<<nnz_blocks, 256>>>(x_rows, x_cols, x_vals,
                                             adj_rows, adj_cols, adj_vals,
                                             ox, oa, cntx, cnta, cx, ca);

    // SpMM1: xw = sparse(x) @ W   (W chunk in smem)
    cudaFuncSetAttribute(spmm1_kernel,
                         cudaFuncAttributeMaxDynamicSharedMemorySize, SMEM1_BYTES);
    spmm1_kernel<<<dim3(148, NCHUNK1), 512, SMEM1_BYTES>>>(ox, cx, W, xw);

    // SpMM2 + ReLU: out = relu(sparse(adj) @ xw), column halves for L2 residency
    const int spmm2_blocks = (N_NODES + 7) / 8;
    spmm2_kernel<<<spmm2_blocks, 256>>>(oa, ca, xw, out, 0);
    spmm2_kernel<<<spmm2_blocks, 256>>>(oa, ca, xw, out, 1);
}

// round 4
// speedup vs baseline: 1.9785x; 1.9785x over previous
#include <cuda_runtime.h>
#include <cuda_fp16.h>

#define N_NODES 100000
#define IN_DIM  1024
#define OUT_DIM 256
#define NNZ_X   3200000
#define NNZ_ADJ 3200000

#define SCAN_B    1024
#define N_SCANBLK ((N_NODES + SCAN_B - 1) / SCAN_B)   // 98

// ---------------- scratch (__device__ globals; no allocs allowed) ----------
__device__ __half g_xw[(size_t)N_NODES * OUT_DIM];     // 51.2 MB (L2-resident)

__device__ int   g_counts_x[N_NODES];
__device__ int   g_counts_a[N_NODES];
__device__ int   g_offs_x[N_NODES + 1];
__device__ int   g_offs_a[N_NODES + 1];
__device__ int   g_bsums_x[N_SCANBLK];
__device__ int   g_bsums_a[N_SCANBLK];
__device__ int2  g_cx[NNZ_X];                          // (col, val-bits)
__device__ int2  g_ca[NNZ_ADJ];

// ---------------- zero both counter arrays ---------------------------------
__global__ void zero2_kernel(int* __restrict__ a, int* __restrict__ b) {
    int i = blockIdx.x * blockDim.x + threadIdx.x;
    int stride = gridDim.x * blockDim.x;
    for (int j = i; j < N_NODES; j += stride) { a[j] = 0; b[j] = 0; }
}

// ---------------- fused histogram of both row arrays ------------------------
__global__ void hist_both_kernel(const int* __restrict__ xr, const int* __restrict__ ar,
                                 int* __restrict__ cx, int* __restrict__ ca) {
    int i = blockIdx.x * blockDim.x + threadIdx.x;
    if (i < NNZ_X)   atomicAdd(&cx[xr[i]], 1);
    if (i < NNZ_ADJ) atomicAdd(&ca[ar[i]], 1);
}

// ---------------- scan A: per-block exclusive scan (both arrays, grid.y) ----
__global__ void scanA_kernel(const int* __restrict__ cx, const int* __restrict__ ca,
                             int* __restrict__ ox, int* __restrict__ oa,
                             int* __restrict__ bx, int* __restrict__ ba) {
    const int* counts = blockIdx.y ? ca : cx;
    int* offs  = blockIdx.y ? oa : ox;
    int* bsums = blockIdx.y ? ba : bx;
    __shared__ int sm[SCAN_B];
    int t = threadIdx.x;
    int i = blockIdx.x * SCAN_B + t;
    int v = (i < N_NODES) ? counts[i] : 0;
    sm[t] = v;
    __syncthreads();
    for (int d = 1; d < SCAN_B; d <<= 1) {
        int add = (t >= d) ? sm[t - d] : 0;
        __syncthreads();
        sm[t] += add;
        __syncthreads();
    }
    int incl = sm[t];
    if (i < N_NODES) offs[i] = incl - v;
    if (t == SCAN_B - 1) bsums[blockIdx.x] = incl;
}

// ---------------- scan B: parallel exclusive scan of 98 block sums ----------
__global__ void scanB_kernel(int* __restrict__ bx, int* __restrict__ ba) {
    int* bsums = blockIdx.x ? ba : bx;
    __shared__ int sm[128];
    int t = threadIdx.x;
    int v = (t < N_SCANBLK) ? bsums[t] : 0;
    sm[t] = v;
    __syncthreads();
    for (int d = 1; d < 128; d <<= 1) {
        int add = (t >= d) ? sm[t - d] : 0;
        __syncthreads();
        sm[t] += add;
        __syncthreads();
    }
    if (t < N_SCANBLK) bsums[t] = sm[t] - v;   // exclusive
}

// ---------------- scan C: add block offsets ---------------------------------
__global__ void scanC_kernel(int* __restrict__ ox, int* __restrict__ oa,
                             const int* __restrict__ bx, const int* __restrict__ ba) {
    int* offs = blockIdx.y ? oa : ox;
    const int* bsums = blockIdx.y ? ba : bx;
    int i = blockIdx.x * SCAN_B + threadIdx.x;
    if (i < N_NODES) offs[i] += bsums[blockIdx.x];
    if (i == 0) offs[N_NODES] = blockIdx.y ? NNZ_ADJ : NNZ_X;
}

// ---------------- fused scatter COO -> CSR (int2 payload) -------------------
__global__ void scatter_both_kernel(
        const int* __restrict__ xr, const int* __restrict__ xc, const float* __restrict__ xv,
        const int* __restrict__ ar, const int* __restrict__ ac, const float* __restrict__ av,
        const int* __restrict__ ox, const int* __restrict__ oa,
        int* __restrict__ cntx, int* __restrict__ cnta,
        int2* __restrict__ cx, int2* __restrict__ ca) {
    int i = blockIdx.x * blockDim.x + threadIdx.x;
    if (i < NNZ_X) {
        int r = xr[i];
        int p = ox[r] + atomicSub(&cntx[r], 1) - 1;
        cx[p] = make_int2(xc[i], __float_as_int(xv[i]));
    }
    if (i < NNZ_ADJ) {
        int r = ar[i];
        int p = oa[r] + atomicSub(&cnta[r], 1) - 1;
        ca[p] = make_int2(ac[i], __float_as_int(av[i]));
    }
}

// ---------------- SpMM1: warp per row, gather W (fp32) -> xw (fp16) ---------
// Lane j owns column pairs (2j, 2j+1) at offsets {0,64,128,192}: float2 gathers,
// half2 stores. fp32 accumulation throughout.
__global__ void __launch_bounds__(256, 8)
spmm1_kernel(const int* __restrict__ offs, const int2* __restrict__ cdata,
             const float* __restrict__ W, __half* __restrict__ xw) {
    int warp = (blockIdx.x * blockDim.x + threadIdx.x) >> 5;
    int lane = threadIdx.x & 31;
    if (warp >= N_NODES) return;

    int beg = offs[warp];
    int end = offs[warp + 1];

    float ax0 = 0.f, ay0 = 0.f, ax1 = 0.f, ay1 = 0.f;
    float ax2 = 0.f, ay2 = 0.f, ax3 = 0.f, ay3 = 0.f;

    for (int base = beg; base < end; base += 32) {
        int k = base + lane;
        int2 cv = (k < end) ? __ldg(&cdata[k]) : make_int2(0, 0);
        int m = min(32, end - base);
        for (int t = 0; t < m; t++) {
            int   cc = __shfl_sync(0xffffffffu, cv.x, t);
            float vv = __int_as_float(__shfl_sync(0xffffffffu, cv.y, t));
            const float2* w2 = reinterpret_cast<const float2*>(W + (size_t)cc * OUT_DIM);
            float2 w0 = __ldg(&w2[lane]);
            float2 w1 = __ldg(&w2[lane + 32]);
            float2 wA = __ldg(&w2[lane + 64]);
            float2 wB = __ldg(&w2[lane + 96]);
            ax0 = fmaf(vv, w0.x, ax0); ay0 = fmaf(vv, w0.y, ay0);
            ax1 = fmaf(vv, w1.x, ax1); ay1 = fmaf(vv, w1.y, ay1);
            ax2 = fmaf(vv, wA.x, ax2); ay2 = fmaf(vv, wA.y, ay2);
            ax3 = fmaf(vv, wB.x, ax3); ay3 = fmaf(vv, wB.y, ay3);
        }
    }

    __half2* d = reinterpret_cast<__half2*>(xw + (size_t)warp * OUT_DIM);
    d[lane]      = __floats2half2_rn(ax0, ay0);
    d[lane + 32] = __floats2half2_rn(ax1, ay1);
    d[lane + 64] = __floats2half2_rn(ax2, ay2);
    d[lane + 96] = __floats2half2_rn(ax3, ay3);
}

// ---------------- SpMM2 + ReLU: warp per row, gather xw (fp16) -> out (fp32)
__global__ void __launch_bounds__(256, 8)
spmm2_kernel(const int* __restrict__ offs, const int2* __restrict__ cdata,
             const __half* __restrict__ xw, float* __restrict__ out) {
    int warp = (blockIdx.x * blockDim.x + threadIdx.x) >> 5;
    int lane = threadIdx.x & 31;
    if (warp >= N_NODES) return;

    int beg = offs[warp];
    int end = offs[warp + 1];

    float ax0 = 0.f, ay0 = 0.f, ax1 = 0.f, ay1 = 0.f;
    float ax2 = 0.f, ay2 = 0.f, ax3 = 0.f, ay3 = 0.f;

    for (int base = beg; base < end; base += 32) {
        int k = base + lane;
        int2 cv = (k < end) ? __ldg(&cdata[k]) : make_int2(0, 0);
        int m = min(32, end - base);
        for (int t = 0; t < m; t++) {
            int   cc = __shfl_sync(0xffffffffu, cv.x, t);
            float vv = __int_as_float(__shfl_sync(0xffffffffu, cv.y, t));
            const __half2* s2 = reinterpret_cast<const __half2*>(xw + (size_t)cc * OUT_DIM);
            float2 s0 = __half22float2(__ldg(&s2[lane]));
            float2 s1 = __half22float2(__ldg(&s2[lane + 32]));
            float2 sA = __half22float2(__ldg(&s2[lane + 64]));
            float2 sB = __half22float2(__ldg(&s2[lane + 96]));
            ax0 = fmaf(vv, s0.x, ax0); ay0 = fmaf(vv, s0.y, ay0);
            ax1 = fmaf(vv, s1.x, ax1); ay1 = fmaf(vv, s1.y, ay1);
            ax2 = fmaf(vv, sA.x, ax2); ay2 = fmaf(vv, sA.y, ay2);
            ax3 = fmaf(vv, sB.x, ax3); ay3 = fmaf(vv, sB.y, ay3);
        }
    }

    float2* d = reinterpret_cast<float2*>(out + (size_t)warp * OUT_DIM);
    d[lane]      = make_float2(fmaxf(ax0, 0.f), fmaxf(ay0, 0.f));
    d[lane + 32] = make_float2(fmaxf(ax1, 0.f), fmaxf(ay1, 0.f));
    d[lane + 64] = make_float2(fmaxf(ax2, 0.f), fmaxf(ay2, 0.f));
    d[lane + 96] = make_float2(fmaxf(ax3, 0.f), fmaxf(ay3, 0.f));
}

// ---------------------------------------------------------------------------
extern "C" void kernel_launch(void* const* d_in, const int* in_sizes, int n_in,
                              void* d_out, int out_size) {
    const int*   x_rows   = (const int*)  d_in[0];
    const int*   x_cols   = (const int*)  d_in[1];
    const float* x_vals   = (const float*)d_in[2];
    const int*   adj_rows = (const int*)  d_in[3];
    const int*   adj_cols = (const int*)  d_in[4];
    const float* adj_vals = (const float*)d_in[5];
    const float* W        = (const float*)d_in[6];
    float*       out      = (float*)d_out;

    __half *xw; int *cntx, *cnta, *ox, *oa, *bx, *ba; int2 *cx, *ca;
    cudaGetSymbolAddress((void**)&xw,   g_xw);
    cudaGetSymbolAddress((void**)&cntx, g_counts_x);
    cudaGetSymbolAddress((void**)&cnta, g_counts_a);
    cudaGetSymbolAddress((void**)&ox,   g_offs_x);
    cudaGetSymbolAddress((void**)&oa,   g_offs_a);
    cudaGetSymbolAddress((void**)&bx,   g_bsums_x);
    cudaGetSymbolAddress((void**)&ba,   g_bsums_a);
    cudaGetSymbolAddress((void**)&cx,   g_cx);
    cudaGetSymbolAddress((void**)&ca,   g_ca);

    const int nnz_blocks = (NNZ_X + 255) / 256;

    // build phase
    zero2_kernel<<<196, 512>>>(cntx, cnta);
    hist_both_kernel<<<nnz_blocks, 256>>>(x_rows, adj_rows, cntx, cnta);
    scanA_kernel<<<dim3(N_SCANBLK, 2), SCAN_B>>>(cntx, cnta, ox, oa, bx, ba);
    scanB_kernel<<<2, 128>>>(bx, ba);
    scanC_kernel<<<dim3(N_SCANBLK, 2), SCAN_B>>>(ox, oa, bx, ba);
    scatter_both_kernel<<<nnz_blocks, 256>>>(x_rows, x_cols, x_vals,
                                             adj_rows, adj_cols, adj_vals,
                                             ox, oa, cntx, cnta, cx, ca);

    // SpMM1: xw(fp16) = sparse(x) @ W
    const int spmm_blocks = (N_NODES * 32 + 255) / 256;   // warp per row
    spmm1_kernel<<<spmm_blocks, 256>>>(ox, cx, W, xw);

    // SpMM2 + ReLU: out = relu(sparse(adj) @ xw)
    spmm2_kernel<<<spmm_blocks, 256>>>(oa, ca, xw, out);
}

// round 5
// speedup vs baseline: 2.1539x; 1.0886x over previous
#include <cuda_runtime.h>
#include <cuda_fp16.h>

#define N_NODES 100000
#define IN_DIM  1024
#define OUT_DIM 256
#define NNZ_X   3200000
#define NNZ_ADJ 3200000

#define SCAN_B    1024
#define N_SCANBLK ((N_NODES + SCAN_B - 1) / SCAN_B)   // 98

// ---------------- scratch (__device__ globals; no allocs allowed) ----------
__device__ __half g_xw[(size_t)N_NODES * OUT_DIM];     // 51.2 MB (L2-resident)
__device__ __half g_wh[IN_DIM * OUT_DIM];              // 512 KB  (L1-friendly)

__device__ int   g_counts_x[N_NODES];
__device__ int   g_counts_a[N_NODES];
__device__ int   g_offs_x[N_NODES + 1];
__device__ int   g_offs_a[N_NODES + 1];
__device__ int   g_bsums_x[N_SCANBLK];
__device__ int   g_bsums_a[N_SCANBLK];
__device__ int2  g_cx[NNZ_X];                          // (col, val-bits)
__device__ int2  g_ca[NNZ_ADJ];

// ---------------- W fp32 -> fp16 -------------------------------------------
__global__ void wcvt_kernel(const float* __restrict__ W, __half* __restrict__ Wh) {
    int i = blockIdx.x * blockDim.x + threadIdx.x;      // over float2 pairs
    if (i < IN_DIM * OUT_DIM / 2) {
        float2 w = reinterpret_cast<const float2*>(W)[i];
        reinterpret_cast<__half2*>(Wh)[i] = __floats2half2_rn(w.x, w.y);
    }
}

// ---------------- zero both counter arrays ---------------------------------
__global__ void zero2_kernel(int* __restrict__ a, int* __restrict__ b) {
    int i = blockIdx.x * blockDim.x + threadIdx.x;
    int stride = gridDim.x * blockDim.x;
    for (int j = i; j < N_NODES; j += stride) { a[j] = 0; b[j] = 0; }
}

// ---------------- fused histogram of both row arrays ------------------------
__global__ void hist_both_kernel(const int* __restrict__ xr, const int* __restrict__ ar,
                                 int* __restrict__ cx, int* __restrict__ ca) {
    int i = blockIdx.x * blockDim.x + threadIdx.x;
    if (i < NNZ_X)   atomicAdd(&cx[xr[i]], 1);
    if (i < NNZ_ADJ) atomicAdd(&ca[ar[i]], 1);
}

// ---------------- scan A: per-block exclusive scan (both arrays, grid.y) ----
__global__ void scanA_kernel(const int* __restrict__ cx, const int* __restrict__ ca,
                             int* __restrict__ ox, int* __restrict__ oa,
                             int* __restrict__ bx, int* __restrict__ ba) {
    const int* counts = blockIdx.y ? ca : cx;
    int* offs  = blockIdx.y ? oa : ox;
    int* bsums = blockIdx.y ? ba : bx;
    __shared__ int sm[SCAN_B];
    int t = threadIdx.x;
    int i = blockIdx.x * SCAN_B + t;
    int v = (i < N_NODES) ? counts[i] : 0;
    sm[t] = v;
    __syncthreads();
    for (int d = 1; d < SCAN_B; d <<= 1) {
        int add = (t >= d) ? sm[t - d] : 0;
        __syncthreads();
        sm[t] += add;
        __syncthreads();
    }
    int incl = sm[t];
    if (i < N_NODES) offs[i] = incl - v;
    if (t == SCAN_B - 1) bsums[blockIdx.x] = incl;
}

// ---------------- scan B: parallel exclusive scan of 98 block sums ----------
__global__ void scanB_kernel(int* __restrict__ bx, int* __restrict__ ba) {
    int* bsums = blockIdx.x ? ba : bx;
    __shared__ int sm[128];
    int t = threadIdx.x;
    int v = (t < N_SCANBLK) ? bsums[t] : 0;
    sm[t] = v;
    __syncthreads();
    for (int d = 1; d < 128; d <<= 1) {
        int add = (t >= d) ? sm[t - d] : 0;
        __syncthreads();
        sm[t] += add;
        __syncthreads();
    }
    if (t < N_SCANBLK) bsums[t] = sm[t] - v;   // exclusive
}

// ---------------- scan C: add block offsets ---------------------------------
__global__ void scanC_kernel(int* __restrict__ ox, int* __restrict__ oa,
                             const int* __restrict__ bx, const int* __restrict__ ba) {
    int* offs = blockIdx.y ? oa : ox;
    const int* bsums = blockIdx.y ? ba : bx;
    int i = blockIdx.x * SCAN_B + threadIdx.x;
    if (i < N_NODES) offs[i] += bsums[blockIdx.x];
    if (i == 0) offs[N_NODES] = blockIdx.y ? NNZ_ADJ : NNZ_X;
}

// ---------------- fused scatter COO -> CSR (int2 payload) -------------------
__global__ void scatter_both_kernel(
        const int* __restrict__ xr, const int* __restrict__ xc, const float* __restrict__ xv,
        const int* __restrict__ ar, const int* __restrict__ ac, const float* __restrict__ av,
        const int* __restrict__ ox, const int* __restrict__ oa,
        int* __restrict__ cntx, int* __restrict__ cnta,
        int2* __restrict__ cx, int2* __restrict__ ca) {
    int i = blockIdx.x * blockDim.x + threadIdx.x;
    if (i < NNZ_X) {
        int r = xr[i];
        int p = ox[r] + atomicSub(&cntx[r], 1) - 1;
        cx[p] = make_int2(xc[i], __float_as_int(xv[i]));
    }
    if (i < NNZ_ADJ) {
        int r = ar[i];
        int p = oa[r] + atomicSub(&cnta[r], 1) - 1;
        ca[p] = make_int2(ac[i], __float_as_int(av[i]));
    }
}

// ---------------- SpMM1: warp per row; fp16 src row, one int4 load per nnz --
// Lane j owns columns [8j, 8j+8). Whole 512B row fetched by one LDG.128/warp.
__global__ void __launch_bounds__(256, 8)
spmm1_kernel(const int* __restrict__ offs, const int2* __restrict__ cdata,
             const __half* __restrict__ Wh, __half* __restrict__ xw) {
    int warp = (blockIdx.x * blockDim.x + threadIdx.x) >> 5;
    int lane = threadIdx.x & 31;
    if (warp >= N_NODES) return;

    int beg = offs[warp];
    int end = offs[warp + 1];

    float a0 = 0.f, a1 = 0.f, a2 = 0.f, a3 = 0.f;
    float a4 = 0.f, a5 = 0.f, a6 = 0.f, a7 = 0.f;

    for (int base = beg; base < end; base += 32) {
        int k = base + lane;
        int2 cv = (k < end) ? __ldg(&cdata[k]) : make_int2(0, 0);
        int m = min(32, end - base);
        for (int t = 0; t < m; t++) {
            int   cc = __shfl_sync(0xffffffffu, cv.x, t);
            float vv = __int_as_float(__shfl_sync(0xffffffffu, cv.y, t));
            int4 wv = __ldg(reinterpret_cast<const int4*>(Wh + (size_t)cc * OUT_DIM) + lane);
            float2 f0 = __half22float2(*reinterpret_cast<__half2*>(&wv.x));
            float2 f1 = __half22float2(*reinterpret_cast<__half2*>(&wv.y));
            float2 f2 = __half22float2(*reinterpret_cast<__half2*>(&wv.z));
            float2 f3 = __half22float2(*reinterpret_cast<__half2*>(&wv.w));
            a0 = fmaf(vv, f0.x, a0); a1 = fmaf(vv, f0.y, a1);
            a2 = fmaf(vv, f1.x, a2); a3 = fmaf(vv, f1.y, a3);
            a4 = fmaf(vv, f2.x, a4); a5 = fmaf(vv, f2.y, a5);
            a6 = fmaf(vv, f3.x, a6); a7 = fmaf(vv, f3.y, a7);
        }
    }

    int4 o;
    __half2 h0 = __floats2half2_rn(a0, a1);
    __half2 h1 = __floats2half2_rn(a2, a3);
    __half2 h2 = __floats2half2_rn(a4, a5);
    __half2 h3 = __floats2half2_rn(a6, a7);
    o.x = *reinterpret_cast<int*>(&h0);
    o.y = *reinterpret_cast<int*>(&h1);
    o.z = *reinterpret_cast<int*>(&h2);
    o.w = *reinterpret_cast<int*>(&h3);
    reinterpret_cast<int4*>(xw + (size_t)warp * OUT_DIM)[lane] = o;
}

// ---------------- SpMM2 + ReLU: same pattern, fp32 out ----------------------
__global__ void __launch_bounds__(256, 8)
spmm2_kernel(const int* __restrict__ offs, const int2* __restrict__ cdata,
             const __half* __restrict__ xw, float* __restrict__ out) {
    int warp = (blockIdx.x * blockDim.x + threadIdx.x) >> 5;
    int lane = threadIdx.x & 31;
    if (warp >= N_NODES) return;

    int beg = offs[warp];
    int end = offs[warp + 1];

    float a0 = 0.f, a1 = 0.f, a2 = 0.f, a3 = 0.f;
    float a4 = 0.f, a5 = 0.f, a6 = 0.f, a7 = 0.f;

    for (int base = beg; base < end; base += 32) {
        int k = base + lane;
        int2 cv = (k < end) ? __ldg(&cdata[k]) : make_int2(0, 0);
        int m = min(32, end - base);
        for (int t = 0; t < m; t++) {
            int   cc = __shfl_sync(0xffffffffu, cv.x, t);
            float vv = __int_as_float(__shfl_sync(0xffffffffu, cv.y, t));
            int4 wv = __ldg(reinterpret_cast<const int4*>(xw + (size_t)cc * OUT_DIM) + lane);
            float2 f0 = __half22float2(*reinterpret_cast<__half2*>(&wv.x));
            float2 f1 = __half22float2(*reinterpret_cast<__half2*>(&wv.y));
            float2 f2 = __half22float2(*reinterpret_cast<__half2*>(&wv.z));
            float2 f3 = __half22float2(*reinterpret_cast<__half2*>(&wv.w));
            a0 = fmaf(vv, f0.x, a0); a1 = fmaf(vv, f0.y, a1);
            a2 = fmaf(vv, f1.x, a2); a3 = fmaf(vv, f1.y, a3);
            a4 = fmaf(vv, f2.x, a4); a5 = fmaf(vv, f2.y, a5);
            a6 = fmaf(vv, f3.x, a6); a7 = fmaf(vv, f3.y, a7);
        }
    }

    float4* d = reinterpret_cast<float4*>(out + (size_t)warp * OUT_DIM) + lane * 2;
    d[0] = make_float4(fmaxf(a0, 0.f), fmaxf(a1, 0.f), fmaxf(a2, 0.f), fmaxf(a3, 0.f));
    d[1] = make_float4(fmaxf(a4, 0.f), fmaxf(a5, 0.f), fmaxf(a6, 0.f), fmaxf(a7, 0.f));
}

// ---------------------------------------------------------------------------
extern "C" void kernel_launch(void* const* d_in, const int* in_sizes, int n_in,
                              void* d_out, int out_size) {
    const int*   x_rows   = (const int*)  d_in[0];
    const int*   x_cols   = (const int*)  d_in[1];
    const float* x_vals   = (const float*)d_in[2];
    const int*   adj_rows = (const int*)  d_in[3];
    const int*   adj_cols = (const int*)  d_in[4];
    const float* adj_vals = (const float*)d_in[5];
    const float* W        = (const float*)d_in[6];
    float*       out      = (float*)d_out;

    __half *xw, *Wh; int *cntx, *cnta, *ox, *oa, *bx, *ba; int2 *cx, *ca;
    cudaGetSymbolAddress((void**)&xw,   g_xw);
    cudaGetSymbolAddress((void**)&Wh,   g_wh);
    cudaGetSymbolAddress((void**)&cntx, g_counts_x);
    cudaGetSymbolAddress((void**)&cnta, g_counts_a);
    cudaGetSymbolAddress((void**)&ox,   g_offs_x);
    cudaGetSymbolAddress((void**)&oa,   g_offs_a);
    cudaGetSymbolAddress((void**)&bx,   g_bsums_x);
    cudaGetSymbolAddress((void**)&ba,   g_bsums_a);
    cudaGetSymbolAddress((void**)&cx,   g_cx);
    cudaGetSymbolAddress((void**)&ca,   g_ca);

    const int nnz_blocks = (NNZ_X + 255) / 256;

    // build phase (+ W convert, overlappable)
    wcvt_kernel<<<(IN_DIM * OUT_DIM / 2 + 255) / 256, 256>>>(W, Wh);
    zero2_kernel<<<196, 512>>>(cntx, cnta);
    hist_both_kernel<<<nnz_blocks, 256>>>(x_rows, adj_rows, cntx, cnta);
    scanA_kernel<<<dim3(N_SCANBLK, 2), SCAN_B>>>(cntx, cnta, ox, oa, bx, ba);
    scanB_kernel<<<2, 128>>>(bx, ba);
    scanC_kernel<<<dim3(N_SCANBLK, 2), SCAN_B>>>(ox, oa, bx, ba);
    scatter_both_kernel<<<nnz_blocks, 256>>>(x_rows, x_cols, x_vals,
                                             adj_rows, adj_cols, adj_vals,
                                             ox, oa, cntx, cnta, cx, ca);

    // SpMM1: xw(fp16) = sparse(x) @ W(fp16)
    const int spmm_blocks = (N_NODES * 32 + 255) / 256;   // warp per row
    spmm1_kernel<<<spmm_blocks, 256>>>(ox, cx, Wh, xw);

    // SpMM2 + ReLU: out = relu(sparse(adj) @ xw)
    spmm2_kernel<<<spmm_blocks, 256>>>(oa, ca, xw, out);
}

// round 6
// speedup vs baseline: 2.2354x; 1.0378x over previous
#include <cuda_runtime.h>
#include <cuda_fp16.h>

#define N_NODES 100000
#define IN_DIM  1024
#define OUT_DIM 256
#define NNZ_X   3200000
#define NNZ_ADJ 3200000

#define SCAN_B    1024
#define N_SCANBLK ((N_NODES + SCAN_B - 1) / SCAN_B)   // 98

// ---------------- scratch (__device__ globals; no allocs allowed) ----------
__device__ __half g_xw[(size_t)N_NODES * OUT_DIM];     // 51.2 MB (L2-resident)
__device__ __half g_wh[IN_DIM * OUT_DIM];              // 512 KB

__device__ int   g_counts_x[N_NODES];
__device__ int   g_counts_a[N_NODES];
__device__ int   g_offs_x[N_NODES + 1];
__device__ int   g_offs_a[N_NODES + 1];
__device__ int   g_bsums_x[N_SCANBLK];
__device__ int   g_bsums_a[N_SCANBLK];
__device__ int2  g_cx[NNZ_X];                          // (col, val-bits)
__device__ int2  g_ca[NNZ_ADJ];

// ---------------- W fp32 -> fp16 -------------------------------------------
__global__ void wcvt_kernel(const float* __restrict__ W, __half* __restrict__ Wh) {
    int i = blockIdx.x * blockDim.x + threadIdx.x;      // over float2 pairs
    if (i < IN_DIM * OUT_DIM / 2) {
        float2 w = __ldcs(reinterpret_cast<const float2*>(W) + i);
        reinterpret_cast<__half2*>(Wh)[i] = __floats2half2_rn(w.x, w.y);
    }
}

// ---------------- zero both counter arrays ---------------------------------
__global__ void zero2_kernel(int* __restrict__ a, int* __restrict__ b) {
    int i = blockIdx.x * blockDim.x + threadIdx.x;
    int stride = gridDim.x * blockDim.x;
    for (int j = i; j < N_NODES; j += stride) { a[j] = 0; b[j] = 0; }
}

// ---------------- histogram of one row array --------------------------------
__global__ void hist_kernel(const int* __restrict__ rows, int* __restrict__ counts, int nnz) {
    int i = blockIdx.x * blockDim.x + threadIdx.x;
    if (i < nnz) atomicAdd(&counts[__ldcs(&rows[i])], 1);
}

// ---------------- scan A: per-block exclusive scan --------------------------
__global__ void scanA_kernel(const int* __restrict__ counts,
                             int* __restrict__ offs, int* __restrict__ bsums) {
    __shared__ int sm[SCAN_B];
    int t = threadIdx.x;
    int i = blockIdx.x * SCAN_B + t;
    int v = (i < N_NODES) ? counts[i] : 0;
    sm[t] = v;
    __syncthreads();
    for (int d = 1; d < SCAN_B; d <<= 1) {
        int add = (t >= d) ? sm[t - d] : 0;
        __syncthreads();
        sm[t] += add;
        __syncthreads();
    }
    int incl = sm[t];
    if (i < N_NODES) offs[i] = incl - v;
    if (t == SCAN_B - 1) bsums[blockIdx.x] = incl;
}

// ---------------- scan B: parallel exclusive scan of 98 block sums ----------
__global__ void scanB_kernel(int* __restrict__ bsums) {
    __shared__ int sm[128];
    int t = threadIdx.x;
    int v = (t < N_SCANBLK) ? bsums[t] : 0;
    sm[t] = v;
    __syncthreads();
    for (int d = 1; d < 128; d <<= 1) {
        int add = (t >= d) ? sm[t - d] : 0;
        __syncthreads();
        sm[t] += add;
        __syncthreads();
    }
    if (t < N_SCANBLK) bsums[t] = sm[t] - v;   // exclusive
}

// ---------------- scan C: add block offsets ---------------------------------
__global__ void scanC_kernel(int* __restrict__ offs, const int* __restrict__ bsums, int total) {
    int i = blockIdx.x * SCAN_B + threadIdx.x;
    if (i < N_NODES) offs[i] += bsums[blockIdx.x];
    if (i == 0) offs[N_NODES] = total;
}

// ---------------- scatter COO -> CSR (int2 payload) --------------------------
// counts[] holds the histogram; atomicSub turns it into a fill cursor.
__global__ void scatter_kernel(const int* __restrict__ rows, const int* __restrict__ cols,
                               const float* __restrict__ vals,
                               const int* __restrict__ offs, int* __restrict__ cnt,
                               int2* __restrict__ cdata, int nnz) {
    int i = blockIdx.x * blockDim.x + threadIdx.x;
    if (i >= nnz) return;
    int r = __ldcs(&rows[i]);
    int p = offs[r] + atomicSub(&cnt[r], 1) - 1;
    cdata[p] = make_int2(__ldcs(&cols[i]), __float_as_int(__ldcs(&vals[i])));
}

// ---------------- SpMM1: warp per row; fp16 W row, one int4 load per nnz ----
__global__ void __launch_bounds__(256, 8)
spmm1_kernel(const int* __restrict__ offs, const int2* __restrict__ cdata,
             const __half* __restrict__ Wh, __half* __restrict__ xw) {
    int warp = (blockIdx.x * blockDim.x + threadIdx.x) >> 5;
    int lane = threadIdx.x & 31;
    if (warp >= N_NODES) return;

    int beg = offs[warp];
    int end = offs[warp + 1];

    float a0 = 0.f, a1 = 0.f, a2 = 0.f, a3 = 0.f;
    float a4 = 0.f, a5 = 0.f, a6 = 0.f, a7 = 0.f;

    for (int base = beg; base < end; base += 32) {
        int k = base + lane;
        int2 cv = (k < end) ? __ldcs(&cdata[k]) : make_int2(0, 0);
        int m = min(32, end - base);
        for (int t = 0; t < m; t++) {
            int   cc = __shfl_sync(0xffffffffu, cv.x, t);
            float vv = __int_as_float(__shfl_sync(0xffffffffu, cv.y, t));
            int4 wv = __ldg(reinterpret_cast<const int4*>(Wh + (size_t)cc * OUT_DIM) + lane);
            float2 f0 = __half22float2(*reinterpret_cast<__half2*>(&wv.x));
            float2 f1 = __half22float2(*reinterpret_cast<__half2*>(&wv.y));
            float2 f2 = __half22float2(*reinterpret_cast<__half2*>(&wv.z));
            float2 f3 = __half22float2(*reinterpret_cast<__half2*>(&wv.w));
            a0 = fmaf(vv, f0.x, a0); a1 = fmaf(vv, f0.y, a1);
            a2 = fmaf(vv, f1.x, a2); a3 = fmaf(vv, f1.y, a3);
            a4 = fmaf(vv, f2.x, a4); a5 = fmaf(vv, f2.y, a5);
            a6 = fmaf(vv, f3.x, a6); a7 = fmaf(vv, f3.y, a7);
        }
    }

    int4 o;
    __half2 h0 = __floats2half2_rn(a0, a1);
    __half2 h1 = __floats2half2_rn(a2, a3);
    __half2 h2 = __floats2half2_rn(a4, a5);
    __half2 h3 = __floats2half2_rn(a6, a7);
    o.x = *reinterpret_cast<int*>(&h0);
    o.y = *reinterpret_cast<int*>(&h1);
    o.z = *reinterpret_cast<int*>(&h2);
    o.w = *reinterpret_cast<int*>(&h3);
    reinterpret_cast<int4*>(xw + (size_t)warp * OUT_DIM)[lane] = o;
}

// ---------------- SpMM2 + ReLU: streaming stores protect xw in L2 -----------
__global__ void __launch_bounds__(256, 8)
spmm2_kernel(const int* __restrict__ offs, const int2* __restrict__ cdata,
             const __half* __restrict__ xw, float* __restrict__ out) {
    int warp = (blockIdx.x * blockDim.x + threadIdx.x) >> 5;
    int lane = threadIdx.x & 31;
    if (warp >= N_NODES) return;

    int beg = offs[warp];
    int end = offs[warp + 1];

    float a0 = 0.f, a1 = 0.f, a2 = 0.f, a3 = 0.f;
    float a4 = 0.f, a5 = 0.f, a6 = 0.f, a7 = 0.f;

    for (int base = beg; base < end; base += 32) {
        int k = base + lane;
        int2 cv = (k < end) ? __ldcs(&cdata[k]) : make_int2(0, 0);
        int m = min(32, end - base);
        for (int t = 0; t < m; t++) {
            int   cc = __shfl_sync(0xffffffffu, cv.x, t);
            float vv = __int_as_float(__shfl_sync(0xffffffffu, cv.y, t));
            int4 wv = __ldg(reinterpret_cast<const int4*>(xw + (size_t)cc * OUT_DIM) + lane);
            float2 f0 = __half22float2(*reinterpret_cast<__half2*>(&wv.x));
            float2 f1 = __half22float2(*reinterpret_cast<__half2*>(&wv.y));
            float2 f2 = __half22float2(*reinterpret_cast<__half2*>(&wv.z));
            float2 f3 = __half22float2(*reinterpret_cast<__half2*>(&wv.w));
            a0 = fmaf(vv, f0.x, a0); a1 = fmaf(vv, f0.y, a1);
            a2 = fmaf(vv, f1.x, a2); a3 = fmaf(vv, f1.y, a3);
            a4 = fmaf(vv, f2.x, a4); a5 = fmaf(vv, f2.y, a5);
            a6 = fmaf(vv, f3.x, a6); a7 = fmaf(vv, f3.y, a7);
        }
    }

    float4* d = reinterpret_cast<float4*>(out + (size_t)warp * OUT_DIM) + lane * 2;
    __stcs(d,     make_float4(fmaxf(a0, 0.f), fmaxf(a1, 0.f), fmaxf(a2, 0.f), fmaxf(a3, 0.f)));
    __stcs(d + 1, make_float4(fmaxf(a4, 0.f), fmaxf(a5, 0.f), fmaxf(a6, 0.f), fmaxf(a7, 0.f)));
}

// ---------------------------------------------------------------------------
extern "C" void kernel_launch(void* const* d_in, const int* in_sizes, int n_in,
                              void* d_out, int out_size) {
    const int*   x_rows   = (const int*)  d_in[0];
    const int*   x_cols   = (const int*)  d_in[1];
    const float* x_vals   = (const float*)d_in[2];
    const int*   adj_rows = (const int*)  d_in[3];
    const int*   adj_cols = (const int*)  d_in[4];
    const float* adj_vals = (const float*)d_in[5];
    const float* W        = (const float*)d_in[6];
    float*       out      = (float*)d_out;

    __half *xw, *Wh; int *cntx, *cnta, *ox, *oa, *bx, *ba; int2 *cx, *ca;
    cudaGetSymbolAddress((void**)&xw,   g_xw);
    cudaGetSymbolAddress((void**)&Wh,   g_wh);
    cudaGetSymbolAddress((void**)&cntx, g_counts_x);
    cudaGetSymbolAddress((void**)&cnta, g_counts_a);
    cudaGetSymbolAddress((void**)&ox,   g_offs_x);
    cudaGetSymbolAddress((void**)&oa,   g_offs_a);
    cudaGetSymbolAddress((void**)&bx,   g_bsums_x);
    cudaGetSymbolAddress((void**)&ba,   g_bsums_a);
    cudaGetSymbolAddress((void**)&cx,   g_cx);
    cudaGetSymbolAddress((void**)&ca,   g_ca);

    // Side stream + fork/join events: created ONCE on the first (uncaptured)
    // correctness call; reused by every capture. Non-blocking so the legacy
    // stream does not implicitly serialize with it.
    static cudaStream_t s2 = nullptr;
    static cudaEvent_t  evFork = nullptr, evJoin = nullptr;
    if (s2 == nullptr) {
        cudaStreamCreateWithFlags(&s2, cudaStreamNonBlocking);
        cudaEventCreateWithFlags(&evFork, cudaEventDisableTiming);
        cudaEventCreateWithFlags(&evJoin, cudaEventDisableTiming);
    }

    const int nnz_blocks = (NNZ_X + 255) / 256;

    // ---- common prefix on main stream, then fork ----
    zero2_kernel<<<196, 512>>>(cntx, cnta);
    cudaEventRecord(evFork, 0);
    cudaStreamWaitEvent(s2, evFork, 0);

    // ---- chain B (adj build + W convert) on side stream: hides under spmm1 ----
    wcvt_kernel<<<(IN_DIM * OUT_DIM / 2 + 255) / 256, 256, 0, s2>>>(W, Wh);
    hist_kernel<<<nnz_blocks, 256, 0, s2>>>(adj_rows, cnta, NNZ_ADJ);
    scanA_kernel<<<N_SCANBLK, SCAN_B, 0, s2>>>(cnta, oa, ba);
    scanB_kernel<<<1, 128, 0, s2>>>(ba);
    scanC_kernel<<<N_SCANBLK, SCAN_B, 0, s2>>>(oa, ba, NNZ_ADJ);
    scatter_kernel<<<nnz_blocks, 256, 0, s2>>>(adj_rows, adj_cols, adj_vals,
                                               oa, cnta, ca, NNZ_ADJ);
    cudaEventRecord(evJoin, s2);

    // ---- chain A (x build + spmm1) on main stream ----
    hist_kernel<<<nnz_blocks, 256>>>(x_rows, cntx, NNZ_X);
    scanA_kernel<<<N_SCANBLK, SCAN_B>>>(cntx, ox, bx);
    scanB_kernel<<<1, 128>>>(bx);
    scanC_kernel<<<N_SCANBLK, SCAN_B>>>(ox, bx, NNZ_X);
    scatter_kernel<<<nnz_blocks, 256>>>(x_rows, x_cols, x_vals,
                                        ox, cntx, cx, NNZ_X);

    const int spmm_blocks = (N_NODES * 32 + 255) / 256;   // warp per row
    spmm1_kernel<<<spmm_blocks, 256>>>(ox, cx, Wh, xw);

    // ---- join, then SpMM2 + ReLU ----
    cudaStreamWaitEvent(0, evJoin, 0);
    spmm2_kernel<<<spmm_blocks, 256>>>(oa, ca, xw, out);
}